// round 1
// baseline (speedup 1.0000x reference)
#include <cuda_runtime.h>

#define BATCH 2048
#define D0 256
#define D1 256
#define D2 256
#define D3 128

// Scratch (device globals: allocation-free per harness rules)
__device__ float g_We0[D1 * D0];
__device__ float g_We1[D2 * D1];
__device__ float g_We2[D3 * D2];
__device__ float g_h1[BATCH * D1];
__device__ float g_h2[BATCH * D2];

__device__ __forceinline__ float tanh_fast(float x) {
    float y;
    asm("tanh.approx.f32 %0, %1;" : "=f"(y) : "f"(x));
    return y;
}

// Precompute effective weights We = atom(W, idx) for all three layers.
// atoms: 0=identity, 1=sin, 2=tanh, 3=square. Accurate math here (only 163K elems).
__global__ void prep_we_kernel(const float* __restrict__ W0, const int* __restrict__ f0,
                               const float* __restrict__ W1, const int* __restrict__ f1,
                               const float* __restrict__ W2, const int* __restrict__ f2) {
    const int total0 = D1 * D0;
    const int total1 = total0 + D2 * D1;
    const int total  = total1 + D3 * D2;
    for (int t = blockIdx.x * blockDim.x + threadIdx.x; t < total;
         t += gridDim.x * blockDim.x) {
        const float* W;
        const int* f;
        float* o;
        int i;
        if (t < total0)      { W = W0; f = f0; o = g_We0; i = t; }
        else if (t < total1) { W = W1; f = f1; o = g_We1; i = t - total0; }
        else                 { W = W2; f = f2; o = g_We2; i = t - total1; }
        float w = W[i];
        int idx = f[i];
        float v = w;                       // identity
        if (idx == 1)      v = sinf(w);
        else if (idx == 2) v = tanhf(w);
        else if (idx == 3) v = w * w;
        o[i] = v;
    }
}

// One layer: h_out[b,o] = sum_i g(h_in[b,i] * We[o,i]) + bias[o]
// g = tanh (TANH=true, hidden layers) or identity (last layer).
// Block = (32,8): tx -> 32 outputs (coalesced stores), ty -> 8 batches.
// We tile staged transposed + padded in smem: We_s[i][tx] conflict-free.
// h_s[ty][i] is warp-uniform (broadcast, no conflicts).
template <int IN, bool TANH>
__global__ __launch_bounds__(256) void layer_kernel(
    const float* __restrict__ h_in,   // [BATCH, IN]
    const float* __restrict__ We,     // [OUT, IN]
    const float* __restrict__ bias,   // [OUT]
    float* __restrict__ h_out,        // [BATCH, OUT]
    int OUT) {
    __shared__ float We_s[IN][33];    // [i][o_local], pad to 33 for conflict-free
    __shared__ float h_s[8][IN];

    const int tx = threadIdx.x;
    const int ty = threadIdx.y;
    const int tid = ty * 32 + tx;
    const int o0 = blockIdx.x * 32;
    const int b0 = blockIdx.y * 8;

    // Stage We tile (32 rows of length IN), transposed into smem.
    // Global reads coalesced over i; smem writes stride-33 words -> conflict-free.
    for (int idx = tid; idx < 32 * IN; idx += 256) {
        int o = idx / IN;
        int i = idx - o * IN;
        We_s[i][o] = We[(o0 + o) * IN + i];
    }
    // Stage h tile (8 rows), linear.
    for (int idx = tid; idx < 8 * IN; idx += 256) {
        int b = idx / IN;
        int i = idx - b * IN;
        h_s[b][i] = h_in[(b0 + b) * IN + i];
    }
    __syncthreads();

    float acc0 = 0.f, acc1 = 0.f;   // two accumulators to relax the FADD chain
#pragma unroll 8
    for (int i = 0; i < IN; i += 2) {
        float z0 = h_s[ty][i]     * We_s[i][tx];
        float z1 = h_s[ty][i + 1] * We_s[i + 1][tx];
        if (TANH) {
            acc0 += tanh_fast(z0);
            acc1 += tanh_fast(z1);
        } else {
            acc0 += z0;
            acc1 += z1;
        }
    }
    h_out[(b0 + ty) * OUT + o0 + tx] = acc0 + acc1 + bias[o0 + tx];
}

extern "C" void kernel_launch(void* const* d_in, const int* in_sizes, int n_in,
                              void* d_out, int out_size) {
    // Resolve input ordering at runtime:
    //   dict order:      x, W0,b0,f0, W1,b1,f1, W2,b2,f2   -> in_sizes[4] = 65536 (W1)
    //   signature order: x, W0,b0, W1,b1, W2,b2, f0,f1,f2  -> in_sizes[4] = 256   (b1)
    const float *x, *W0, *b0, *W1, *b1, *W2, *b2;
    const int *f0, *f1, *f2;
    x = (const float*)d_in[0];
    if (in_sizes[4] == 256) {
        // signature order
        W0 = (const float*)d_in[1]; b0 = (const float*)d_in[2];
        W1 = (const float*)d_in[3]; b1 = (const float*)d_in[4];
        W2 = (const float*)d_in[5]; b2 = (const float*)d_in[6];
        f0 = (const int*)d_in[7];  f1 = (const int*)d_in[8];  f2 = (const int*)d_in[9];
    } else {
        // dict (setup_inputs) order
        W0 = (const float*)d_in[1]; b0 = (const float*)d_in[2]; f0 = (const int*)d_in[3];
        W1 = (const float*)d_in[4]; b1 = (const float*)d_in[5]; f1 = (const int*)d_in[6];
        W2 = (const float*)d_in[7]; b2 = (const float*)d_in[8]; f2 = (const int*)d_in[9];
    }

    float *dWe0, *dWe1, *dWe2, *dh1, *dh2;
    cudaGetSymbolAddress((void**)&dWe0, g_We0);
    cudaGetSymbolAddress((void**)&dWe1, g_We1);
    cudaGetSymbolAddress((void**)&dWe2, g_We2);
    cudaGetSymbolAddress((void**)&dh1, g_h1);
    cudaGetSymbolAddress((void**)&dh2, g_h2);

    float* out = (float*)d_out;

    prep_we_kernel<<<160, 256>>>(W0, f0, W1, f1, W2, f2);

    dim3 blk(32, 8);
    // Layer 0: x[2048,256] -> h1[2048,256], tanh
    layer_kernel<D0, true><<<dim3(D1 / 32, BATCH / 8), blk>>>(x, dWe0, b0, dh1, D1);
    // Layer 1: h1 -> h2[2048,256], tanh
    layer_kernel<D1, true><<<dim3(D2 / 32, BATCH / 8), blk>>>(dh1, dWe1, b1, dh2, D2);
    // Layer 2: h2 -> out[2048,128], identity (plain GEMM)
    layer_kernel<D2, false><<<dim3(D3 / 32, BATCH / 8), blk>>>(dh2, dWe2, b2, out, D3);
}